// round 1
// baseline (speedup 1.0000x reference)
#include <cuda_runtime.h>

// ---------------------------------------------------------------------------
// AggNet: 4x ChebConv(K=3) + node MLP + 2x edge MLP on a 200K-node / 3.2M-edge
// random graph.  Strategy:
//  * Build CSR (sorted by col) once per launch via counting sort -> SPMM is a
//    deterministic per-node gather (no float atomics).
//  * Layer 4 uses the spmm/matmul commute: spmm(x)@W == spmm(x@W), reducing
//    128 edge-feature passes to 3.
//  * Instance-norm is fused into the SPMM gather and the combine matmul
//    (normalized input is never materialized).
// ---------------------------------------------------------------------------

static constexpr int NMAX = 200000;
static constexpr int EMAX = 3200000;

// -------- static device scratch (no runtime allocation allowed) ------------
__device__ float g_wn[EMAX];        // sorted-by-col normalized edge weights
__device__ int   g_rows[EMAX];      // sorted-by-col source node ids
__device__ int   g_off[NMAX + 1];   // CSR offsets
__device__ int   g_cursor[NMAX];
__device__ int   g_cnt[NMAX];
__device__ float g_deg[NMAX];
__device__ float g_rdis[NMAX];
__device__ int   g_part[1024];
__device__ int   g_partex[1024];

__device__ float g_x1[NMAX * 4];
__device__ float g_x2[NMAX * 16];
__device__ float g_x3[NMAX * 64];
__device__ float g_tx1[NMAX * 16];
__device__ float g_s2[NMAX * 16];
__device__ float g_u[NMAX];
__device__ float g_q[NMAX];
__device__ float g_r[NMAX];
__device__ float g_tq[NMAX];
__device__ float g_s[NMAX];
__device__ float g_t[NMAX];
__device__ float g_sums[192];       // per-layer raw sum/sumsq slices
__device__ float g_stats[192];      // per-layer mean/rstd slices

// ---------------------------------------------------------------------------
__global__ void k_zero(int N) {
    int i = blockIdx.x * blockDim.x + threadIdx.x;
    if (i < N) { g_cnt[i] = 0; g_deg[i] = 0.f; }
    if (i < 192) g_sums[i] = 0.f;
}

__global__ void k_count(const int* __restrict__ ei, const float* __restrict__ ea, int E) {
    int e = blockIdx.x * blockDim.x + threadIdx.x;
    if (e >= E) return;
    int r = ei[e];
    int c = ei[E + e];
    atomicAdd(&g_cnt[c], 1);
    atomicAdd(&g_deg[r], ea[e]);
}

__global__ void k_rdis(int N) {
    int n = blockIdx.x * blockDim.x + threadIdx.x;
    if (n >= N) return;
    float d = g_deg[n];
    g_rdis[n] = (d > 0.f) ? rsqrtf(d) : 0.f;
}

// ---- 3-kernel exclusive scan of g_cnt -> g_off (chunk = 512) --------------
__global__ void k_scanA(int n) {
    __shared__ int sd[512];
    int i = blockIdx.x * 512 + threadIdx.x;
    int v = (i < n) ? g_cnt[i] : 0;
    sd[threadIdx.x] = v;
    __syncthreads();
    for (int s = 1; s < 512; s <<= 1) {
        int t = (threadIdx.x >= s) ? sd[threadIdx.x - s] : 0;
        __syncthreads();
        sd[threadIdx.x] += t;
        __syncthreads();
    }
    if (i < n) g_off[i] = sd[threadIdx.x] - v;      // block-local exclusive
    if (threadIdx.x == 511) g_part[blockIdx.x] = sd[511];
}

__global__ void k_scanB(int nb) {
    __shared__ int sd[1024];
    int v = ((int)threadIdx.x < nb) ? g_part[threadIdx.x] : 0;
    sd[threadIdx.x] = v;
    __syncthreads();
    for (int s = 1; s < 1024; s <<= 1) {
        int t = (threadIdx.x >= s) ? sd[threadIdx.x - s] : 0;
        __syncthreads();
        sd[threadIdx.x] += t;
        __syncthreads();
    }
    g_partex[threadIdx.x] = sd[threadIdx.x] - v;    // exclusive
}

__global__ void k_scanC(int n, int e) {
    int i = blockIdx.x * blockDim.x + threadIdx.x;
    if (i < n) {
        int o = g_off[i] + g_partex[i >> 9];
        g_off[i] = o;
        g_cursor[i] = o;
    }
    if (i == 0) g_off[n] = e;
}

__global__ void k_scatter(const int* __restrict__ ei, const float* __restrict__ ea, int E) {
    int e = blockIdx.x * blockDim.x + threadIdx.x;
    if (e >= E) return;
    int r = ei[e];
    int c = ei[E + e];
    float w = ea[e];
    int p = atomicAdd(&g_cursor[c], 1);
    g_rows[p] = r;
    g_wn[p] = -g_rdis[r] * w * g_rdis[c];
}

// ---- instance-norm statistics ---------------------------------------------
template<int F>
__global__ void k_reduce(const float* __restrict__ x, float* __restrict__ sums, int N) {
    constexpr int G = 256 / F;
    int f = threadIdx.x & (F - 1);
    int g = threadIdx.x / F;
    float s = 0.f, s2 = 0.f;
    for (int n = blockIdx.x * G + g; n < N; n += gridDim.x * G) {
        float v = x[n * F + f];
        s += v;
        s2 += v * v;
    }
    __shared__ float rs[256], rq[256];
    rs[threadIdx.x] = s;
    rq[threadIdx.x] = s2;
    __syncthreads();
    for (int step = 128; step >= F; step >>= 1) {
        if ((int)threadIdx.x < step) {
            rs[threadIdx.x] += rs[threadIdx.x + step];
            rq[threadIdx.x] += rq[threadIdx.x + step];
        }
        __syncthreads();
    }
    if ((int)threadIdx.x < F) {
        atomicAdd(&sums[f], rs[f]);
        atomicAdd(&sums[F + f], rq[f]);
    }
}

__global__ void k_finalize(const float* __restrict__ sums, float* __restrict__ stats,
                           int F, int N) {
    int f = threadIdx.x;
    if (f >= F) return;
    float inv = 1.f / (float)N;
    float m = sums[f] * inv;
    float var = sums[F + f] * inv - m * m;
    if (var < 0.f) var = 0.f;
    stats[f] = m;
    stats[F + f] = rsqrtf(var + 1e-5f);
}

// ---- SPMM: out[c] = sum_{e in CSR[c]} wn[e] * z[rows[e]] -------------------
// F=1: one thread per node.
template<bool NORM>
__global__ void k_spmm1(const float* __restrict__ z, const float* __restrict__ stats,
                        float* __restrict__ out, int N) {
    int n = blockIdx.x * blockDim.x + threadIdx.x;
    if (n >= N) return;
    float m = 0.f, rs = 1.f;
    if (NORM) { m = stats[0]; rs = stats[1]; }
    int e0 = g_off[n], e1 = g_off[n + 1];
    float acc = 0.f;
    for (int e = e0; e < e1; e++) {
        float v = __ldg(&z[__ldg(&g_rows[e])]);
        if (NORM) v = (v - m) * rs;
        acc = fmaf(__ldg(&g_wn[e]), v, acc);
    }
    out[n] = acc;
}

// F in {4,16}: one warp per node; 32/F edges processed in parallel.
template<int F, bool NORM>
__global__ void k_spmmF(const float* __restrict__ z, const float* __restrict__ stats,
                        float* __restrict__ out, int N) {
    constexpr int EPW = 32 / F;
    int wid = (blockIdx.x * blockDim.x + threadIdx.x) >> 5;
    if (wid >= N) return;
    int lane = threadIdx.x & 31;
    int f = lane & (F - 1);
    int g = lane / F;
    float m = 0.f, rs = 1.f;
    if (NORM) { m = stats[f]; rs = stats[F + f]; }
    int e0 = __ldg(&g_off[wid]);
    int e1 = __ldg(&g_off[wid + 1]);
    float acc = 0.f;
    for (int e = e0 + g; e < e1; e += EPW) {
        int r = __ldg(&g_rows[e]);
        float w = __ldg(&g_wn[e]);
        float v = __ldg(&z[r * F + f]);
        if (NORM) v = (v - m) * rs;
        acc = fmaf(w, v, acc);
    }
#pragma unroll
    for (int s = 16; s >= F; s >>= 1) acc += __shfl_xor_sync(0xffffffffu, acc, s);
    if (lane < F) out[wid * F + f] = acc;
}

// ---- Cheb combine: out = relu(xin@(W0-W2) + Tx1@W1 + 2*S2@W2 + b) ----------
template<int FI, int FO, int M>
__global__ void k_combine(const float* __restrict__ x, const float* __restrict__ stats,
                          const float* __restrict__ tx1, const float* __restrict__ s2,
                          const float* __restrict__ W, const float* __restrict__ b,
                          float* __restrict__ out, int N) {
    __shared__ float sW[3 * FI * FO];
    __shared__ float sb[FO];
    __shared__ float sm[FI], srv[FI];
    for (int i = threadIdx.x; i < FI * FO; i += blockDim.x) {
        float w0 = W[i], w1 = W[FI * FO + i], w2 = W[2 * FI * FO + i];
        sW[i] = w0 - w2;
        sW[FI * FO + i] = w1;
        sW[2 * FI * FO + i] = 2.f * w2;
    }
    if ((int)threadIdx.x < FO) sb[threadIdx.x] = b[threadIdx.x];
    if ((int)threadIdx.x < FI) {
        sm[threadIdx.x] = stats[threadIdx.x];
        srv[threadIdx.x] = stats[FI + threadIdx.x];
    }
    __syncthreads();
    int base = blockIdx.x * blockDim.x * M + threadIdx.x;
    int nn[M];
    float acc[M][FO];
#pragma unroll
    for (int i = 0; i < M; i++) {
        nn[i] = base + i * blockDim.x;
#pragma unroll
        for (int j = 0; j < FO; j++) acc[i][j] = sb[j];
    }
#pragma unroll 1
    for (int k = 0; k < FI; k++) {
        float xv[M], tv[M], sv[M];
#pragma unroll
        for (int i = 0; i < M; i++) {
            xv[i] = 0.f; tv[i] = 0.f; sv[i] = 0.f;
            if (nn[i] < N) {
                xv[i] = (x[nn[i] * FI + k] - sm[k]) * srv[k];
                tv[i] = tx1[nn[i] * FI + k];
                sv[i] = s2[nn[i] * FI + k];
            }
        }
#pragma unroll
        for (int j = 0; j < FO; j++) {
            float w0 = sW[k * FO + j];
            float w1 = sW[FI * FO + k * FO + j];
            float w2 = sW[2 * FI * FO + k * FO + j];
#pragma unroll
            for (int i = 0; i < M; i++)
                acc[i][j] = fmaf(xv[i], w0, fmaf(tv[i], w1, fmaf(sv[i], w2, acc[i][j])));
        }
    }
#pragma unroll
    for (int i = 0; i < M; i++)
        if (nn[i] < N) {
#pragma unroll
            for (int j = 0; j < FO; j++) out[nn[i] * FO + j] = fmaxf(acc[i][j], 0.f);
        }
}

// ---- layer4 projections: u = xin@(W0-W2), q = xin@W1, r = xin@W2 -----------
__global__ void k_uqr(const float* __restrict__ x3, const float* __restrict__ stats,
                      const float* __restrict__ W, int N) {
    __shared__ float wu[64], wq[64], wr[64], sm[64], srv[64];
    int t = threadIdx.x;
    if (t < 64) {
        float w0 = W[t], w1 = W[64 + t], w2 = W[128 + t];
        wu[t] = w0 - w2; wq[t] = w1; wr[t] = w2;
        sm[t] = stats[t]; srv[t] = stats[64 + t];
    }
    __syncthreads();
    int n = blockIdx.x * blockDim.x + t;
    if (n >= N) return;
    float u = 0.f, q = 0.f, r = 0.f;
#pragma unroll
    for (int k = 0; k < 64; k++) {
        float xin = (x3[n * 64 + k] - sm[k]) * srv[k];
        u = fmaf(xin, wu[k], u);
        q = fmaf(xin, wq[k], q);
        r = fmaf(xin, wr[k], r);
    }
    g_u[n] = u; g_q[n] = q; g_r[n] = r;
}

// ---- node MLP: xs(85) -> 40 -> 16 -> 1; x4 computed inline -----------------
__global__ void __launch_bounds__(128) k_nodemlp(
    const float* __restrict__ l1W, const float* __restrict__ l1b,
    const float* __restrict__ l2W, const float* __restrict__ l2b,
    const float* __restrict__ l3W, const float* __restrict__ l3b,
    const float* __restrict__ c4b,
    float* __restrict__ xo, int N) {
    __shared__ float sW1[85 * 40], sb1[40], sW2[40 * 16], sb2[16], sW3[16], sb3[1], sb4[1];
    for (int i = threadIdx.x; i < 85 * 40; i += blockDim.x) sW1[i] = l1W[i];
    for (int i = threadIdx.x; i < 40 * 16; i += blockDim.x) sW2[i] = l2W[i];
    if (threadIdx.x < 40) sb1[threadIdx.x] = l1b[threadIdx.x];
    if (threadIdx.x < 16) { sb2[threadIdx.x] = l2b[threadIdx.x]; sW3[threadIdx.x] = l3W[threadIdx.x]; }
    if (threadIdx.x == 0) { sb3[0] = l3b[0]; sb4[0] = c4b[0]; }
    __syncthreads();

    int base = blockIdx.x * blockDim.x * 2 + threadIdx.x;
    int n0 = base, n1 = base + blockDim.x;
    bool v0ok = n0 < N, v1ok = n1 < N;

    float h1[2][40];
#pragma unroll
    for (int j = 0; j < 40; j++) { h1[0][j] = sb1[j]; h1[1][j] = sb1[j]; }

#pragma unroll 1
    for (int k = 0; k < 4; k++) {
        float a = v0ok ? g_x1[n0 * 4 + k] : 0.f;
        float bb = v1ok ? g_x1[n1 * 4 + k] : 0.f;
#pragma unroll
        for (int j = 0; j < 40; j++) {
            float w = sW1[k * 40 + j];
            h1[0][j] = fmaf(a, w, h1[0][j]);
            h1[1][j] = fmaf(bb, w, h1[1][j]);
        }
    }
#pragma unroll 1
    for (int k = 0; k < 16; k++) {
        float a = v0ok ? g_x2[n0 * 16 + k] : 0.f;
        float bb = v1ok ? g_x2[n1 * 16 + k] : 0.f;
#pragma unroll
        for (int j = 0; j < 40; j++) {
            float w = sW1[(4 + k) * 40 + j];
            h1[0][j] = fmaf(a, w, h1[0][j]);
            h1[1][j] = fmaf(bb, w, h1[1][j]);
        }
    }
#pragma unroll 1
    for (int k = 0; k < 64; k++) {
        float a = v0ok ? g_x3[n0 * 64 + k] : 0.f;
        float bb = v1ok ? g_x3[n1 * 64 + k] : 0.f;
#pragma unroll
        for (int j = 0; j < 40; j++) {
            float w = sW1[(20 + k) * 40 + j];
            h1[0][j] = fmaf(a, w, h1[0][j]);
            h1[1][j] = fmaf(bb, w, h1[1][j]);
        }
    }
    {   // x4 = relu(u + Tq + 2*t + cheb4_b)
        float a = v0ok ? fmaxf(g_u[n0] + g_tq[n0] + 2.f * g_t[n0] + sb4[0], 0.f) : 0.f;
        float bb = v1ok ? fmaxf(g_u[n1] + g_tq[n1] + 2.f * g_t[n1] + sb4[0], 0.f) : 0.f;
#pragma unroll
        for (int j = 0; j < 40; j++) {
            float w = sW1[84 * 40 + j];
            h1[0][j] = fmaf(a, w, h1[0][j]);
            h1[1][j] = fmaf(bb, w, h1[1][j]);
        }
    }
#pragma unroll
    for (int j = 0; j < 40; j++) { h1[0][j] = fmaxf(h1[0][j], 0.f); h1[1][j] = fmaxf(h1[1][j], 0.f); }

    float h2[2][16];
#pragma unroll
    for (int j = 0; j < 16; j++) { h2[0][j] = sb2[j]; h2[1][j] = sb2[j]; }
#pragma unroll
    for (int k = 0; k < 40; k++) {
        float a = h1[0][k], bb = h1[1][k];
#pragma unroll
        for (int j = 0; j < 16; j++) {
            float w = sW2[k * 16 + j];
            h2[0][j] = fmaf(a, w, h2[0][j]);
            h2[1][j] = fmaf(bb, w, h2[1][j]);
        }
    }
    float o0 = sb3[0], o1 = sb3[0];
#pragma unroll
    for (int k = 0; k < 16; k++) {
        float w = sW3[k];
        o0 = fmaf(fmaxf(h2[0][k], 0.f), w, o0);
        o1 = fmaf(fmaxf(h2[1][k], 0.f), w, o1);
    }
    if (v0ok) xo[n0] = fmaxf(o0, 0.f);
    if (v1ok) xo[n1] = fmaxf(o1, 0.f);
}

// ---- edge MLPs -------------------------------------------------------------
__device__ __forceinline__ float edge_mlp(float s, float d, float a,
                                          const float* __restrict__ w1,
                                          const float* __restrict__ b1,
                                          const float* __restrict__ g,
                                          const float* __restrict__ be,
                                          const float* __restrict__ w2,
                                          const float* __restrict__ b2) {
    float h0 = fmaf(s, __ldg(&w1[0]), fmaf(d, __ldg(&w1[2]), fmaf(a, __ldg(&w1[4]), __ldg(&b1[0]))));
    float h1 = fmaf(s, __ldg(&w1[1]), fmaf(d, __ldg(&w1[3]), fmaf(a, __ldg(&w1[5]), __ldg(&b1[1]))));
    h0 = fmaxf(h0, 0.f);
    h1 = fmaxf(h1, 0.f);
    float m = 0.5f * (h0 + h1);
    float d0 = h0 - m, d1 = h1 - m;
    float var = 0.5f * (d0 * d0 + d1 * d1);
    float rs = rsqrtf(var + 1e-5f);
    h0 = fmaf(d0 * rs, __ldg(&g[0]), 0.f) + __ldg(&be[0]);
    h1 = fmaf(d1 * rs, __ldg(&g[1]), 0.f) + __ldg(&be[1]);
    return fmaf(h0, __ldg(&w2[0]), fmaf(h1, __ldg(&w2[1]), __ldg(&b2[0])));
}

__global__ void k_edge(const int* __restrict__ ei, const float* __restrict__ ea,
                       const float* __restrict__ xo,
                       const float* __restrict__ w11, const float* __restrict__ b11,
                       const float* __restrict__ g1, const float* __restrict__ be1,
                       const float* __restrict__ w12, const float* __restrict__ b12,
                       const float* __restrict__ w21, const float* __restrict__ b21,
                       const float* __restrict__ g2, const float* __restrict__ be2,
                       const float* __restrict__ w22, const float* __restrict__ b22,
                       float* __restrict__ out, int E) {
    int e = blockIdx.x * blockDim.x + threadIdx.x;
    if (e >= E) return;
    int r = ei[e];
    int c = ei[E + e];
    float s = __ldg(&xo[r]);
    float d = __ldg(&xo[c]);
    float a = ea[e];
    float o1 = fmaxf(edge_mlp(s, d, a, w11, b11, g1, be1, w12, b12), 0.f);
    float o2 = fmaxf(edge_mlp(s, d, o1, w21, b21, g2, be2, w22, b22), 0.f);
    out[e] = o2;
}

// ---------------------------------------------------------------------------
extern "C" void kernel_launch(void* const* d_in, const int* in_sizes, int n_in,
                              void* d_out, int out_size) {
    (void)n_in; (void)out_size;
    const float* x   = (const float*)d_in[0];
    const int*   ei  = (const int*)d_in[1];
    const float* ea  = (const float*)d_in[2];
    const float* c1W = (const float*)d_in[3];  const float* c1b = (const float*)d_in[4];
    const float* c2W = (const float*)d_in[5];  const float* c2b = (const float*)d_in[6];
    const float* c3W = (const float*)d_in[7];  const float* c3b = (const float*)d_in[8];
    const float* c4W = (const float*)d_in[9];  const float* c4b = (const float*)d_in[10];
    const float* l1W = (const float*)d_in[11]; const float* l1b = (const float*)d_in[12];
    const float* l2W = (const float*)d_in[13]; const float* l2b = (const float*)d_in[14];
    const float* l3W = (const float*)d_in[15]; const float* l3b = (const float*)d_in[16];
    const float* e1w1 = (const float*)d_in[17]; const float* e1b1 = (const float*)d_in[18];
    const float* e1g  = (const float*)d_in[19]; const float* e1be = (const float*)d_in[20];
    const float* e1w2 = (const float*)d_in[21]; const float* e1b2 = (const float*)d_in[22];
    const float* e2w1 = (const float*)d_in[23]; const float* e2b1 = (const float*)d_in[24];
    const float* e2g  = (const float*)d_in[25]; const float* e2be = (const float*)d_in[26];
    const float* e2w2 = (const float*)d_in[27]; const float* e2b2 = (const float*)d_in[28];

    int N = in_sizes[0];
    int E = in_sizes[1] / 2;
    float* out = (float*)d_out;
    float* xo = out;          // first N outputs
    float* eaout = out + N;   // next E outputs

    // device addresses of scratch symbols we pass as kernel args
    void* p;
    float *sums, *stats, *x1, *x2, *x3, *tx1, *s2, *q, *rr, *ss;
    cudaGetSymbolAddress(&p, g_sums);  sums  = (float*)p;
    cudaGetSymbolAddress(&p, g_stats); stats = (float*)p;
    cudaGetSymbolAddress(&p, g_x1);  x1  = (float*)p;
    cudaGetSymbolAddress(&p, g_x2);  x2  = (float*)p;
    cudaGetSymbolAddress(&p, g_x3);  x3  = (float*)p;
    cudaGetSymbolAddress(&p, g_tx1); tx1 = (float*)p;
    cudaGetSymbolAddress(&p, g_s2);  s2  = (float*)p;
    cudaGetSymbolAddress(&p, g_q);   q   = (float*)p;
    cudaGetSymbolAddress(&p, g_r);   rr  = (float*)p;
    cudaGetSymbolAddress(&p, g_s);   ss  = (float*)p;
    float *tq, *tt;
    cudaGetSymbolAddress(&p, g_tq);  tq  = (float*)p;
    cudaGetSymbolAddress(&p, g_t);   tt  = (float*)p;

    int gN  = (N + 255) / 256;
    int gE  = (E + 255) / 256;
    int gW  = (N * 32 + 255) / 256;   // warp-per-node kernels
    int gC2 = (N + 255) / 256;        // combine M=2, B=128 -> 256 nodes/block
    int NB  = (N + 511) / 512;
    const int RG = 512;               // reduction grid

    // stats slice offsets: L1@0 (2), L2@2 (8), L3@10 (32), L4@42 (128)
    float* su1 = sums + 0;  float* st1 = stats + 0;
    float* su2 = sums + 2;  float* st2 = stats + 2;
    float* su3 = sums + 10; float* st3 = stats + 10;
    float* su4 = sums + 42; float* st4 = stats + 42;

    // ---- preprocessing: degrees, CSR by col, normalized weights ----
    k_zero<<<gN, 256>>>(N);
    k_count<<<gE, 256>>>(ei, ea, E);
    k_rdis<<<gN, 256>>>(N);
    k_scanA<<<NB, 512>>>(N);
    k_scanB<<<1, 1024>>>(NB);
    k_scanC<<<gN, 256>>>(N, E);
    k_scatter<<<gE, 256>>>(ei, ea, E);

    // ---- layer 1: F 1 -> 4 ----
    k_reduce<1><<<RG, 256>>>(x, su1, N);
    k_finalize<<<1, 32>>>(su1, st1, 1, N);
    k_spmm1<true><<<gN, 256>>>(x, st1, tx1, N);
    k_spmm1<false><<<gN, 256>>>(tx1, nullptr, s2, N);
    k_combine<1, 4, 1><<<gN, 256>>>(x, st1, tx1, s2, c1W, c1b, x1, N);

    // ---- layer 2: F 4 -> 16 ----
    k_reduce<4><<<RG, 256>>>(x1, su2, N);
    k_finalize<<<1, 32>>>(su2, st2, 4, N);
    k_spmmF<4, true><<<gW, 256>>>(x1, st2, tx1, N);
    k_spmmF<4, false><<<gW, 256>>>(tx1, nullptr, s2, N);
    k_combine<4, 16, 2><<<gC2, 128>>>(x1, st2, tx1, s2, c2W, c2b, x2, N);

    // ---- layer 3: F 16 -> 64 ----
    k_reduce<16><<<RG, 256>>>(x2, su3, N);
    k_finalize<<<1, 32>>>(su3, st3, 16, N);
    k_spmmF<16, true><<<gW, 256>>>(x2, st3, tx1, N);
    k_spmmF<16, false><<<gW, 256>>>(tx1, nullptr, s2, N);
    k_combine<16, 64, 2><<<gC2, 128>>>(x2, st3, tx1, s2, c3W, c3b, x3, N);

    // ---- layer 4: F 64 -> 1 via spmm/matmul commute ----
    k_reduce<64><<<RG, 256>>>(x3, su4, N);
    k_finalize<<<1, 64>>>(su4, st4, 64, N);
    k_uqr<<<gN, 256>>>(x3, st4, c4W, N);
    k_spmm1<false><<<gN, 256>>>(q, nullptr, tq, N);   // Tq = spmm(q)
    k_spmm1<false><<<gN, 256>>>(rr, nullptr, ss, N);  // s  = spmm(r)
    k_spmm1<false><<<gN, 256>>>(ss, nullptr, tt, N);  // t  = spmm(s)

    // ---- node MLP (x4 inline) and edge MLPs ----
    k_nodemlp<<<gC2, 128>>>(l1W, l1b, l2W, l2b, l3W, l3b, c4b, xo, N);
    k_edge<<<gE, 256>>>(ei, ea, xo,
                        e1w1, e1b1, e1g, e1be, e1w2, e1b2,
                        e2w1, e2b1, e2g, e2be, e2w2, e2b2,
                        eaout, E);
}

// round 3
// speedup vs baseline: 1.0762x; 1.0762x over previous
#include <cuda_runtime.h>

// ---------------------------------------------------------------------------
// AggNet: 4x ChebConv(K=3) + node MLP + 2x edge MLP, N=200K, E=3.2M.
// R2 (resubmit after infra failure): packed (row,wn) edge records, vectorized
// sub-warp SPMM, layer-4 pair-SPMM (3 passes -> 2).
// ---------------------------------------------------------------------------

static constexpr int NMAX = 200000;
static constexpr int EMAX = 3200000;

// -------- static device scratch ---------------------------------------------
__device__ int2  g_edge[EMAX];      // (row, wn-bits) sorted by col
__device__ int   g_off[NMAX + 1];
__device__ int   g_cursor[NMAX];
__device__ int   g_cnt[NMAX];
__device__ float g_deg[NMAX];
__device__ float g_rdis[NMAX];
__device__ int   g_part[1024];
__device__ int   g_partex[1024];

__device__ float g_x1[NMAX * 4];
__device__ float g_x2[NMAX * 16];
__device__ float g_x3[NMAX * 64];
__device__ float g_tx1[NMAX * 16];
__device__ float g_s2[NMAX * 16];
__device__ float g_u[NMAX];
__device__ float g_qr[NMAX * 2];    // (q, r) interleaved
__device__ float g_tqs[NMAX * 2];   // (Tq, s) interleaved
__device__ float g_t[NMAX];
__device__ float g_sums[192];
__device__ float g_stats[192];

// ---------------------------------------------------------------------------
__global__ void k_zero(int N) {
    int i = blockIdx.x * blockDim.x + threadIdx.x;
    if (i < N) { g_cnt[i] = 0; g_deg[i] = 0.f; }
    if (i < 192) g_sums[i] = 0.f;
}

__global__ void k_count(const int* __restrict__ ei, const float* __restrict__ ea, int E) {
    int e = blockIdx.x * blockDim.x + threadIdx.x;
    if (e >= E) return;
    int r = ei[e];
    int c = ei[E + e];
    atomicAdd(&g_cnt[c], 1);
    atomicAdd(&g_deg[r], ea[e]);
}

__global__ void k_rdis(int N) {
    int n = blockIdx.x * blockDim.x + threadIdx.x;
    if (n >= N) return;
    float d = g_deg[n];
    g_rdis[n] = (d > 0.f) ? rsqrtf(d) : 0.f;
}

// ---- 3-kernel exclusive scan ----------------------------------------------
__global__ void k_scanA(int n) {
    __shared__ int sd[512];
    int i = blockIdx.x * 512 + threadIdx.x;
    int v = (i < n) ? g_cnt[i] : 0;
    sd[threadIdx.x] = v;
    __syncthreads();
    for (int s = 1; s < 512; s <<= 1) {
        int t = (threadIdx.x >= s) ? sd[threadIdx.x - s] : 0;
        __syncthreads();
        sd[threadIdx.x] += t;
        __syncthreads();
    }
    if (i < n) g_off[i] = sd[threadIdx.x] - v;
    if (threadIdx.x == 511) g_part[blockIdx.x] = sd[511];
}

__global__ void k_scanB(int nb) {
    __shared__ int sd[1024];
    int v = ((int)threadIdx.x < nb) ? g_part[threadIdx.x] : 0;
    sd[threadIdx.x] = v;
    __syncthreads();
    for (int s = 1; s < 1024; s <<= 1) {
        int t = (threadIdx.x >= s) ? sd[threadIdx.x - s] : 0;
        __syncthreads();
        sd[threadIdx.x] += t;
        __syncthreads();
    }
    g_partex[threadIdx.x] = sd[threadIdx.x] - v;
}

__global__ void k_scanC(int n, int e) {
    int i = blockIdx.x * blockDim.x + threadIdx.x;
    if (i < n) {
        int o = g_off[i] + g_partex[i >> 9];
        g_off[i] = o;
        g_cursor[i] = o;
    }
    if (i == 0) g_off[n] = e;
}

__global__ void k_scatter(const int* __restrict__ ei, const float* __restrict__ ea, int E) {
    int e = blockIdx.x * blockDim.x + threadIdx.x;
    if (e >= E) return;
    int r = ei[e];
    int c = ei[E + e];
    float w = ea[e];
    int p = atomicAdd(&g_cursor[c], 1);
    g_edge[p] = make_int2(r, __float_as_int(-g_rdis[r] * w * g_rdis[c]));
}

// ---- instance-norm statistics ---------------------------------------------
template<int F>
__global__ void k_reduce(const float* __restrict__ x, float* __restrict__ sums, int N) {
    constexpr int G = 256 / F;
    int f = threadIdx.x & (F - 1);
    int g = threadIdx.x / F;
    float s = 0.f, s2 = 0.f;
    for (int n = blockIdx.x * G + g; n < N; n += gridDim.x * G) {
        float v = x[n * F + f];
        s += v;
        s2 += v * v;
    }
    __shared__ float rs[256], rq[256];
    rs[threadIdx.x] = s;
    rq[threadIdx.x] = s2;
    __syncthreads();
    for (int step = 128; step >= F; step >>= 1) {
        if ((int)threadIdx.x < step) {
            rs[threadIdx.x] += rs[threadIdx.x + step];
            rq[threadIdx.x] += rq[threadIdx.x + step];
        }
        __syncthreads();
    }
    if ((int)threadIdx.x < F) {
        atomicAdd(&sums[f], rs[f]);
        atomicAdd(&sums[F + f], rq[f]);
    }
}

__global__ void k_finalize(const float* __restrict__ sums, float* __restrict__ stats,
                           int F, int N) {
    int f = threadIdx.x;
    if (f >= F) return;
    float inv = 1.f / (float)N;
    float m = sums[f] * inv;
    float var = sums[F + f] * inv - m * m;
    if (var < 0.f) var = 0.f;
    stats[f] = m;
    stats[F + f] = rsqrtf(var + 1e-5f);
}

// ---- generic vectorized SPMM ----------------------------------------------
// GROUP lanes cooperate on one node.  Each "edge slot" is LPE = F/VEC lanes,
// each lane loading VEC consecutive floats.  EPI = GROUP/LPE edges in flight.
template<int F, int VEC, int GROUP, bool NORM>
__global__ void k_spmm(const float* __restrict__ z, const float* __restrict__ stats,
                       float* __restrict__ out, int N, int zs, int os) {
    constexpr int LPE = F / VEC;
    constexpr int EPI = GROUP / LPE;
    constexpr int NPW = 32 / GROUP;

    int lane = threadIdx.x & 31;
    int wid  = (blockIdx.x * blockDim.x + threadIdx.x) >> 5;
    int sub  = lane / GROUP;          // node slot within warp
    int gl   = lane % GROUP;
    int eg   = gl / LPE;              // edge slot
    int fl   = gl % LPE;              // feature slot

    int node = wid * NPW + sub;

    float m[VEC], rv[VEC];
#pragma unroll
    for (int i = 0; i < VEC; i++) { m[i] = 0.f; rv[i] = 1.f; }
    if (NORM) {
#pragma unroll
        for (int i = 0; i < VEC; i++) {
            m[i]  = stats[fl * VEC + i];
            rv[i] = stats[F + fl * VEC + i];
        }
    }

    int e0 = 0, e1 = 0;
    if (node < N) { e0 = g_off[node]; e1 = g_off[node + 1]; }

    float acc[VEC];
#pragma unroll
    for (int i = 0; i < VEC; i++) acc[i] = 0.f;

    for (int e = e0 + eg; e < e1; e += EPI) {
        int2 ed = g_edge[e];
        float w = __int_as_float(ed.y);
        const float* zp = z + (size_t)ed.x * zs + fl * VEC;
        float v[VEC];
        if (VEC == 4) {
            float4 t = *reinterpret_cast<const float4*>(zp);
            v[0] = t.x; v[1] = t.y; v[2] = t.z; v[3] = t.w;
        } else if (VEC == 2) {
            float2 t = *reinterpret_cast<const float2*>(zp);
            v[0] = t.x; v[1] = t.y;
        } else {
            v[0] = *zp;
        }
#pragma unroll
        for (int i = 0; i < VEC; i++) {
            float vi = NORM ? (v[i] - m[i]) * rv[i] : v[i];
            acc[i] = fmaf(w, vi, acc[i]);
        }
    }

    // reduce across edge slots (strides LPE .. GROUP/2 stay within the group)
#pragma unroll
    for (int s = LPE; s < GROUP; s <<= 1) {
#pragma unroll
        for (int i = 0; i < VEC; i++)
            acc[i] += __shfl_xor_sync(0xffffffffu, acc[i], s);
    }

    if (node < N && eg == 0) {
        float* op = out + (size_t)node * os + fl * VEC;
        if (VEC == 4) {
            *reinterpret_cast<float4*>(op) = make_float4(acc[0], acc[1], acc[2], acc[3]);
        } else if (VEC == 2) {
            *reinterpret_cast<float2*>(op) = make_float2(acc[0], acc[1]);
        } else {
            *op = acc[0];
        }
    }
}

// ---- Cheb combine: out = relu(xin@(W0-W2) + Tx1@W1 + 2*S2@W2 + b) ----------
template<int FI, int FO, int M>
__global__ void k_combine(const float* __restrict__ x, const float* __restrict__ stats,
                          const float* __restrict__ tx1, const float* __restrict__ s2,
                          const float* __restrict__ W, const float* __restrict__ b,
                          float* __restrict__ out, int N) {
    __shared__ float sW[3 * FI * FO];
    __shared__ float sb[FO];
    __shared__ float sm[FI], srv[FI];
    for (int i = threadIdx.x; i < FI * FO; i += blockDim.x) {
        float w0 = W[i], w1 = W[FI * FO + i], w2 = W[2 * FI * FO + i];
        sW[i] = w0 - w2;
        sW[FI * FO + i] = w1;
        sW[2 * FI * FO + i] = 2.f * w2;
    }
    if ((int)threadIdx.x < FO) sb[threadIdx.x] = b[threadIdx.x];
    if ((int)threadIdx.x < FI) {
        sm[threadIdx.x] = stats[threadIdx.x];
        srv[threadIdx.x] = stats[FI + threadIdx.x];
    }
    __syncthreads();
    int base = blockIdx.x * blockDim.x * M + threadIdx.x;
    int nn[M];
    float acc[M][FO];
#pragma unroll
    for (int i = 0; i < M; i++) {
        nn[i] = base + i * blockDim.x;
#pragma unroll
        for (int j = 0; j < FO; j++) acc[i][j] = sb[j];
    }
#pragma unroll 1
    for (int k = 0; k < FI; k++) {
        float xv[M], tv[M], sv[M];
#pragma unroll
        for (int i = 0; i < M; i++) {
            xv[i] = 0.f; tv[i] = 0.f; sv[i] = 0.f;
            if (nn[i] < N) {
                xv[i] = (x[nn[i] * FI + k] - sm[k]) * srv[k];
                tv[i] = tx1[nn[i] * FI + k];
                sv[i] = s2[nn[i] * FI + k];
            }
        }
#pragma unroll
        for (int j = 0; j < FO; j++) {
            float w0 = sW[k * FO + j];
            float w1 = sW[FI * FO + k * FO + j];
            float w2 = sW[2 * FI * FO + k * FO + j];
#pragma unroll
            for (int i = 0; i < M; i++)
                acc[i][j] = fmaf(xv[i], w0, fmaf(tv[i], w1, fmaf(sv[i], w2, acc[i][j])));
        }
    }
#pragma unroll
    for (int i = 0; i < M; i++)
        if (nn[i] < N) {
#pragma unroll
            for (int j = 0; j < FO; j++) out[nn[i] * FO + j] = fmaxf(acc[i][j], 0.f);
        }
}

// ---- layer4 projections: u = xin@(W0-W2), (q,r) = (xin@W1, xin@W2) ---------
__global__ void k_uqr(const float* __restrict__ x3, const float* __restrict__ stats,
                      const float* __restrict__ W, int N) {
    __shared__ float wu[64], wq[64], wr[64], sm[64], srv[64];
    int t = threadIdx.x;
    if (t < 64) {
        float w0 = W[t], w1 = W[64 + t], w2 = W[128 + t];
        wu[t] = w0 - w2; wq[t] = w1; wr[t] = w2;
        sm[t] = stats[t]; srv[t] = stats[64 + t];
    }
    __syncthreads();
    int n = blockIdx.x * blockDim.x + t;
    if (n >= N) return;
    float u = 0.f, q = 0.f, r = 0.f;
#pragma unroll
    for (int k = 0; k < 64; k++) {
        float xin = (x3[n * 64 + k] - sm[k]) * srv[k];
        u = fmaf(xin, wu[k], u);
        q = fmaf(xin, wq[k], q);
        r = fmaf(xin, wr[k], r);
    }
    g_u[n] = u;
    *reinterpret_cast<float2*>(&g_qr[n * 2]) = make_float2(q, r);
}

// ---- node MLP: xs(85) -> 40 -> 16 -> 1; x4 computed inline -----------------
__global__ void __launch_bounds__(128) k_nodemlp(
    const float* __restrict__ l1W, const float* __restrict__ l1b,
    const float* __restrict__ l2W, const float* __restrict__ l2b,
    const float* __restrict__ l3W, const float* __restrict__ l3b,
    const float* __restrict__ c4b,
    float* __restrict__ xo, int N) {
    __shared__ float sW1[85 * 40], sb1[40], sW2[40 * 16], sb2[16], sW3[16], sb3[1], sb4[1];
    for (int i = threadIdx.x; i < 85 * 40; i += blockDim.x) sW1[i] = l1W[i];
    for (int i = threadIdx.x; i < 40 * 16; i += blockDim.x) sW2[i] = l2W[i];
    if (threadIdx.x < 40) sb1[threadIdx.x] = l1b[threadIdx.x];
    if (threadIdx.x < 16) { sb2[threadIdx.x] = l2b[threadIdx.x]; sW3[threadIdx.x] = l3W[threadIdx.x]; }
    if (threadIdx.x == 0) { sb3[0] = l3b[0]; sb4[0] = c4b[0]; }
    __syncthreads();

    int base = blockIdx.x * blockDim.x * 2 + threadIdx.x;
    int n0 = base, n1 = base + blockDim.x;
    bool v0ok = n0 < N, v1ok = n1 < N;

    float h1[2][40];
#pragma unroll
    for (int j = 0; j < 40; j++) { h1[0][j] = sb1[j]; h1[1][j] = sb1[j]; }

#pragma unroll 1
    for (int k = 0; k < 4; k++) {
        float a = v0ok ? g_x1[n0 * 4 + k] : 0.f;
        float bb = v1ok ? g_x1[n1 * 4 + k] : 0.f;
#pragma unroll
        for (int j = 0; j < 40; j++) {
            float w = sW1[k * 40 + j];
            h1[0][j] = fmaf(a, w, h1[0][j]);
            h1[1][j] = fmaf(bb, w, h1[1][j]);
        }
    }
#pragma unroll 1
    for (int k = 0; k < 16; k++) {
        float a = v0ok ? g_x2[n0 * 16 + k] : 0.f;
        float bb = v1ok ? g_x2[n1 * 16 + k] : 0.f;
#pragma unroll
        for (int j = 0; j < 40; j++) {
            float w = sW1[(4 + k) * 40 + j];
            h1[0][j] = fmaf(a, w, h1[0][j]);
            h1[1][j] = fmaf(bb, w, h1[1][j]);
        }
    }
#pragma unroll 1
    for (int k = 0; k < 64; k++) {
        float a = v0ok ? g_x3[n0 * 64 + k] : 0.f;
        float bb = v1ok ? g_x3[n1 * 64 + k] : 0.f;
#pragma unroll
        for (int j = 0; j < 40; j++) {
            float w = sW1[(20 + k) * 40 + j];
            h1[0][j] = fmaf(a, w, h1[0][j]);
            h1[1][j] = fmaf(bb, w, h1[1][j]);
        }
    }
    {   // x4 = relu(u + Tq + 2*t + cheb4_b)
        float a = v0ok ? fmaxf(g_u[n0] + g_tqs[n0 * 2] + 2.f * g_t[n0] + sb4[0], 0.f) : 0.f;
        float bb = v1ok ? fmaxf(g_u[n1] + g_tqs[n1 * 2] + 2.f * g_t[n1] + sb4[0], 0.f) : 0.f;
#pragma unroll
        for (int j = 0; j < 40; j++) {
            float w = sW1[84 * 40 + j];
            h1[0][j] = fmaf(a, w, h1[0][j]);
            h1[1][j] = fmaf(bb, w, h1[1][j]);
        }
    }
#pragma unroll
    for (int j = 0; j < 40; j++) { h1[0][j] = fmaxf(h1[0][j], 0.f); h1[1][j] = fmaxf(h1[1][j], 0.f); }

    float h2[2][16];
#pragma unroll
    for (int j = 0; j < 16; j++) { h2[0][j] = sb2[j]; h2[1][j] = sb2[j]; }
#pragma unroll
    for (int k = 0; k < 40; k++) {
        float a = h1[0][k], bb = h1[1][k];
#pragma unroll
        for (int j = 0; j < 16; j++) {
            float w = sW2[k * 16 + j];
            h2[0][j] = fmaf(a, w, h2[0][j]);
            h2[1][j] = fmaf(bb, w, h2[1][j]);
        }
    }
    float o0 = sb3[0], o1 = sb3[0];
#pragma unroll
    for (int k = 0; k < 16; k++) {
        float w = sW3[k];
        o0 = fmaf(fmaxf(h2[0][k], 0.f), w, o0);
        o1 = fmaf(fmaxf(h2[1][k], 0.f), w, o1);
    }
    if (v0ok) xo[n0] = fmaxf(o0, 0.f);
    if (v1ok) xo[n1] = fmaxf(o1, 0.f);
}

// ---- edge MLPs -------------------------------------------------------------
__device__ __forceinline__ float edge_mlp(float s, float d, float a,
                                          const float* __restrict__ w1,
                                          const float* __restrict__ b1,
                                          const float* __restrict__ g,
                                          const float* __restrict__ be,
                                          const float* __restrict__ w2,
                                          const float* __restrict__ b2) {
    float h0 = fmaf(s, __ldg(&w1[0]), fmaf(d, __ldg(&w1[2]), fmaf(a, __ldg(&w1[4]), __ldg(&b1[0]))));
    float h1 = fmaf(s, __ldg(&w1[1]), fmaf(d, __ldg(&w1[3]), fmaf(a, __ldg(&w1[5]), __ldg(&b1[1]))));
    h0 = fmaxf(h0, 0.f);
    h1 = fmaxf(h1, 0.f);
    float m = 0.5f * (h0 + h1);
    float d0 = h0 - m, d1 = h1 - m;
    float var = 0.5f * (d0 * d0 + d1 * d1);
    float rs = rsqrtf(var + 1e-5f);
    h0 = fmaf(d0 * rs, __ldg(&g[0]), 0.f) + __ldg(&be[0]);
    h1 = fmaf(d1 * rs, __ldg(&g[1]), 0.f) + __ldg(&be[1]);
    return fmaf(h0, __ldg(&w2[0]), fmaf(h1, __ldg(&w2[1]), __ldg(&b2[0])));
}

__global__ void k_edge(const int* __restrict__ ei, const float* __restrict__ ea,
                       const float* __restrict__ xo,
                       const float* __restrict__ w11, const float* __restrict__ b11,
                       const float* __restrict__ g1, const float* __restrict__ be1,
                       const float* __restrict__ w12, const float* __restrict__ b12,
                       const float* __restrict__ w21, const float* __restrict__ b21,
                       const float* __restrict__ g2, const float* __restrict__ be2,
                       const float* __restrict__ w22, const float* __restrict__ b22,
                       float* __restrict__ out, int E) {
    int e = blockIdx.x * blockDim.x + threadIdx.x;
    if (e >= E) return;
    int r = ei[e];
    int c = ei[E + e];
    float s = __ldg(&xo[r]);
    float d = __ldg(&xo[c]);
    float a = ea[e];
    float o1 = fmaxf(edge_mlp(s, d, a, w11, b11, g1, be1, w12, b12), 0.f);
    float o2 = fmaxf(edge_mlp(s, d, o1, w21, b21, g2, be2, w22, b22), 0.f);
    out[e] = o2;
}

// ---------------------------------------------------------------------------
extern "C" void kernel_launch(void* const* d_in, const int* in_sizes, int n_in,
                              void* d_out, int out_size) {
    (void)n_in; (void)out_size;
    const float* x   = (const float*)d_in[0];
    const int*   ei  = (const int*)d_in[1];
    const float* ea  = (const float*)d_in[2];
    const float* c1W = (const float*)d_in[3];  const float* c1b = (const float*)d_in[4];
    const float* c2W = (const float*)d_in[5];  const float* c2b = (const float*)d_in[6];
    const float* c3W = (const float*)d_in[7];  const float* c3b = (const float*)d_in[8];
    const float* c4W = (const float*)d_in[9];  const float* c4b = (const float*)d_in[10];
    const float* l1W = (const float*)d_in[11]; const float* l1b = (const float*)d_in[12];
    const float* l2W = (const float*)d_in[13]; const float* l2b = (const float*)d_in[14];
    const float* l3W = (const float*)d_in[15]; const float* l3b = (const float*)d_in[16];
    const float* e1w1 = (const float*)d_in[17]; const float* e1b1 = (const float*)d_in[18];
    const float* e1g  = (const float*)d_in[19]; const float* e1be = (const float*)d_in[20];
    const float* e1w2 = (const float*)d_in[21]; const float* e1b2 = (const float*)d_in[22];
    const float* e2w1 = (const float*)d_in[23]; const float* e2b1 = (const float*)d_in[24];
    const float* e2g  = (const float*)d_in[25]; const float* e2be = (const float*)d_in[26];
    const float* e2w2 = (const float*)d_in[27]; const float* e2b2 = (const float*)d_in[28];

    int N = in_sizes[0];
    int E = in_sizes[1] / 2;
    float* out = (float*)d_out;
    float* xo = out;
    float* eaout = out + N;

    void* p;
    float *sums, *stats, *x1, *x2, *x3, *tx1, *s2, *qr, *tqs, *tt;
    cudaGetSymbolAddress(&p, g_sums);  sums  = (float*)p;
    cudaGetSymbolAddress(&p, g_stats); stats = (float*)p;
    cudaGetSymbolAddress(&p, g_x1);  x1  = (float*)p;
    cudaGetSymbolAddress(&p, g_x2);  x2  = (float*)p;
    cudaGetSymbolAddress(&p, g_x3);  x3  = (float*)p;
    cudaGetSymbolAddress(&p, g_tx1); tx1 = (float*)p;
    cudaGetSymbolAddress(&p, g_s2);  s2  = (float*)p;
    cudaGetSymbolAddress(&p, g_qr);  qr  = (float*)p;
    cudaGetSymbolAddress(&p, g_tqs); tqs = (float*)p;
    cudaGetSymbolAddress(&p, g_t);   tt  = (float*)p;

    int gN  = (N + 255) / 256;
    int gE  = (E + 255) / 256;
    int gC2 = (N + 255) / 256;
    int NB  = (N + 511) / 512;
    const int RG = 512;

    auto spmm_grid = [](int n, int group) {
        int npw = 32 / group;
        long long warps = (n + npw - 1) / npw;
        return (int)((warps * 32 + 255) / 256);
    };

    float* su1 = sums + 0;  float* st1 = stats + 0;
    float* su2 = sums + 2;  float* st2 = stats + 2;
    float* su3 = sums + 10; float* st3 = stats + 10;
    float* su4 = sums + 42; float* st4 = stats + 42;

    // ---- preprocessing ----
    k_zero<<<gN, 256>>>(N);
    k_count<<<gE, 256>>>(ei, ea, E);
    k_rdis<<<gN, 256>>>(N);
    k_scanA<<<NB, 512>>>(N);
    k_scanB<<<1, 1024>>>(NB);
    k_scanC<<<gN, 256>>>(N, E);
    k_scatter<<<gE, 256>>>(ei, ea, E);

    // ---- layer 1: 1 -> 4 ----
    k_reduce<1><<<RG, 256>>>(x, su1, N);
    k_finalize<<<1, 32>>>(su1, st1, 1, N);
    k_spmm<1, 1, 4, true ><<<spmm_grid(N, 4), 256>>>(x,   st1, tx1, N, 1, 1);
    k_spmm<1, 1, 4, false><<<spmm_grid(N, 4), 256>>>(tx1, nullptr, s2, N, 1, 1);
    k_combine<1, 4, 1><<<gN, 256>>>(x, st1, tx1, s2, c1W, c1b, x1, N);

    // ---- layer 2: 4 -> 16 ----
    k_reduce<4><<<RG, 256>>>(x1, su2, N);
    k_finalize<<<1, 32>>>(su2, st2, 4, N);
    k_spmm<4, 4, 16, true ><<<spmm_grid(N, 16), 256>>>(x1,  st2, tx1, N, 4, 4);
    k_spmm<4, 4, 16, false><<<spmm_grid(N, 16), 256>>>(tx1, nullptr, s2, N, 4, 4);
    k_combine<4, 16, 2><<<gC2, 128>>>(x1, st2, tx1, s2, c2W, c2b, x2, N);

    // ---- layer 3: 16 -> 64 ----
    k_reduce<16><<<RG, 256>>>(x2, su3, N);
    k_finalize<<<1, 32>>>(su3, st3, 16, N);
    k_spmm<16, 4, 32, true ><<<spmm_grid(N, 32), 256>>>(x2,  st3, tx1, N, 16, 16);
    k_spmm<16, 4, 32, false><<<spmm_grid(N, 32), 256>>>(tx1, nullptr, s2, N, 16, 16);
    k_combine<16, 64, 2><<<gC2, 128>>>(x2, st3, tx1, s2, c3W, c3b, x3, N);

    // ---- layer 4: 64 -> 1 via spmm/matmul commute ----
    k_reduce<64><<<RG, 256>>>(x3, su4, N);
    k_finalize<<<1, 64>>>(su4, st4, 64, N);
    k_uqr<<<gN, 256>>>(x3, st4, c4W, N);
    k_spmm<2, 2, 8, false><<<spmm_grid(N, 8), 256>>>(qr, nullptr, tqs, N, 2, 2);      // (Tq, s)
    k_spmm<1, 1, 4, false><<<spmm_grid(N, 4), 256>>>(tqs + 1, nullptr, tt, N, 2, 1);  // t = spmm(s)

    // ---- node MLP and edge MLPs ----
    k_nodemlp<<<gC2, 128>>>(l1W, l1b, l2W, l2b, l3W, l3b, c4b, xo, N);
    k_edge<<<gE, 256>>>(ei, ea, xo,
                        e1w1, e1b1, e1g, e1be, e1w2, e1b2,
                        e2w1, e2b1, e2g, e2be, e2w2, e2b2,
                        eaout, E);
}

// round 4
// speedup vs baseline: 1.1637x; 1.0813x over previous
#include <cuda_runtime.h>
#include <cuda_fp16.h>

// ---------------------------------------------------------------------------
// AggNet: 4x ChebConv(K=3) + node MLP + 2x edge MLP, N=200K, E=3.2M.
// R4: layer-3 (F=16) SPMM path moves to fp16 storage (prenormalized input,
// half intermediates) -> 32B/edge gathers, half the LDGs; dedicated half
// combine; rdis folded into scanC.
// ---------------------------------------------------------------------------

static constexpr int NMAX = 200000;
static constexpr int EMAX = 3200000;

// -------- static device scratch ---------------------------------------------
__device__ int2  g_edge[EMAX];      // (row, wn-bits) sorted by col
__device__ int   g_off[NMAX + 1];
__device__ int   g_cursor[NMAX];
__device__ int   g_cnt[NMAX];
__device__ float g_deg[NMAX];
__device__ float g_rdis[NMAX];
__device__ int   g_part[1024];
__device__ int   g_partex[1024];

__device__ float g_x1[NMAX * 4];
__device__ float g_x2[NMAX * 16];
__device__ float g_x3[NMAX * 64];
__device__ float g_tx1[NMAX * 16];
__device__ float g_s2[NMAX * 16];
__device__ __align__(16) __half g_xn3[NMAX * 16];  // normalized x2, fp16
__device__ __align__(16) __half g_th3[NMAX * 16];  // Tx1 (layer3), fp16
__device__ __align__(16) __half g_sh3[NMAX * 16];  // spmm(Tx1) (layer3), fp16
__device__ float g_u[NMAX];
__device__ float g_qr[NMAX * 2];    // (q, r) interleaved
__device__ float g_tqs[NMAX * 2];   // (Tq, s) interleaved
__device__ float g_t[NMAX];
__device__ float g_sums[192];
__device__ float g_stats[192];

// ---------------------------------------------------------------------------
__global__ void k_zero(int N) {
    int i = blockIdx.x * blockDim.x + threadIdx.x;
    if (i < N) { g_cnt[i] = 0; g_deg[i] = 0.f; }
    if (i < 192) g_sums[i] = 0.f;
}

__global__ void k_count(const int* __restrict__ ei, const float* __restrict__ ea, int E) {
    int e = blockIdx.x * blockDim.x + threadIdx.x;
    if (e >= E) return;
    int r = ei[e];
    int c = ei[E + e];
    atomicAdd(&g_cnt[c], 1);
    atomicAdd(&g_deg[r], ea[e]);
}

// ---- 3-kernel exclusive scan ----------------------------------------------
__global__ void k_scanA(int n) {
    __shared__ int sd[512];
    int i = blockIdx.x * 512 + threadIdx.x;
    int v = (i < n) ? g_cnt[i] : 0;
    sd[threadIdx.x] = v;
    __syncthreads();
    for (int s = 1; s < 512; s <<= 1) {
        int t = (threadIdx.x >= s) ? sd[threadIdx.x - s] : 0;
        __syncthreads();
        sd[threadIdx.x] += t;
        __syncthreads();
    }
    if (i < n) g_off[i] = sd[threadIdx.x] - v;
    if (threadIdx.x == 511) g_part[blockIdx.x] = sd[511];
}

__global__ void k_scanB(int nb) {
    __shared__ int sd[1024];
    int v = ((int)threadIdx.x < nb) ? g_part[threadIdx.x] : 0;
    sd[threadIdx.x] = v;
    __syncthreads();
    for (int s = 1; s < 1024; s <<= 1) {
        int t = (threadIdx.x >= s) ? sd[threadIdx.x - s] : 0;
        __syncthreads();
        sd[threadIdx.x] += t;
        __syncthreads();
    }
    g_partex[threadIdx.x] = sd[threadIdx.x] - v;
}

__global__ void k_scanC(int n, int e) {
    int i = blockIdx.x * blockDim.x + threadIdx.x;
    if (i < n) {
        int o = g_off[i] + g_partex[i >> 9];
        g_off[i] = o;
        g_cursor[i] = o;
        float d = g_deg[i];
        g_rdis[i] = (d > 0.f) ? rsqrtf(d) : 0.f;
    }
    if (i == 0) g_off[n] = e;
}

__global__ void k_scatter(const int* __restrict__ ei, const float* __restrict__ ea, int E) {
    int e = blockIdx.x * blockDim.x + threadIdx.x;
    if (e >= E) return;
    int r = ei[e];
    int c = ei[E + e];
    float w = ea[e];
    int p = atomicAdd(&g_cursor[c], 1);
    g_edge[p] = make_int2(r, __float_as_int(-g_rdis[r] * w * g_rdis[c]));
}

// ---- instance-norm statistics ---------------------------------------------
template<int F>
__global__ void k_reduce(const float* __restrict__ x, float* __restrict__ sums, int N) {
    constexpr int G = 256 / F;
    int f = threadIdx.x & (F - 1);
    int g = threadIdx.x / F;
    float s = 0.f, s2 = 0.f;
    for (int n = blockIdx.x * G + g; n < N; n += gridDim.x * G) {
        float v = x[n * F + f];
        s += v;
        s2 += v * v;
    }
    __shared__ float rs[256], rq[256];
    rs[threadIdx.x] = s;
    rq[threadIdx.x] = s2;
    __syncthreads();
    for (int step = 128; step >= F; step >>= 1) {
        if ((int)threadIdx.x < step) {
            rs[threadIdx.x] += rs[threadIdx.x + step];
            rq[threadIdx.x] += rq[threadIdx.x + step];
        }
        __syncthreads();
    }
    if ((int)threadIdx.x < F) {
        atomicAdd(&sums[f], rs[f]);
        atomicAdd(&sums[F + f], rq[f]);
    }
}

__global__ void k_finalize(const float* __restrict__ sums, float* __restrict__ stats,
                           int F, int N) {
    int f = threadIdx.x;
    if (f >= F) return;
    float inv = 1.f / (float)N;
    float m = sums[f] * inv;
    float var = sums[F + f] * inv - m * m;
    if (var < 0.f) var = 0.f;
    stats[f] = m;
    stats[F + f] = rsqrtf(var + 1e-5f);
}

// ---- prenormalize x2 -> half (F=16), half2 per thread ----------------------
__global__ void k_prenorm16(const float* __restrict__ x2, const float* __restrict__ st,
                            __half* __restrict__ xn, int Ntot8) {
    int i = blockIdx.x * blockDim.x + threadIdx.x;   // over N*8 half2 slots
    if (i >= Ntot8) return;
    int f0 = (i & 7) * 2;
    float2 v = reinterpret_cast<const float2*>(x2)[i];
    float a = (v.x - __ldg(&st[f0]))     * __ldg(&st[16 + f0]);
    float b = (v.y - __ldg(&st[f0 + 1])) * __ldg(&st[16 + f0 + 1]);
    reinterpret_cast<__half2*>(xn)[i] = __floats2half2_rn(a, b);
}

// ---- layer-3 SPMM, fp16 in/out: one warp per node, LPE=2, EPI=16 -----------
__global__ void k_spmm16h(const __half* __restrict__ z, __half* __restrict__ out, int N) {
    int lane = threadIdx.x & 31;
    int node = (blockIdx.x * blockDim.x + threadIdx.x) >> 5;
    int eg = lane >> 1;         // edge slot 0..15
    int fl = lane & 1;          // feature half (8 features each)

    int e0 = 0, e1 = 0;
    if (node < N) { e0 = g_off[node]; e1 = g_off[node + 1]; }

    float acc[8];
#pragma unroll
    for (int i = 0; i < 8; i++) acc[i] = 0.f;

    for (int e = e0 + eg; e < e1; e += 16) {
        int2 ed = g_edge[e];
        float w = __int_as_float(ed.y);
        int4 t = *reinterpret_cast<const int4*>(z + (size_t)ed.x * 16 + fl * 8);
        __half2 h0 = *reinterpret_cast<__half2*>(&t.x);
        __half2 h1 = *reinterpret_cast<__half2*>(&t.y);
        __half2 h2 = *reinterpret_cast<__half2*>(&t.z);
        __half2 h3 = *reinterpret_cast<__half2*>(&t.w);
        float2 f0 = __half22float2(h0);
        float2 f1 = __half22float2(h1);
        float2 f2 = __half22float2(h2);
        float2 f3 = __half22float2(h3);
        acc[0] = fmaf(w, f0.x, acc[0]);
        acc[1] = fmaf(w, f0.y, acc[1]);
        acc[2] = fmaf(w, f1.x, acc[2]);
        acc[3] = fmaf(w, f1.y, acc[3]);
        acc[4] = fmaf(w, f2.x, acc[4]);
        acc[5] = fmaf(w, f2.y, acc[5]);
        acc[6] = fmaf(w, f3.x, acc[6]);
        acc[7] = fmaf(w, f3.y, acc[7]);
    }

    // reduce across edge slots (strides 2..16 keep fl fixed)
#pragma unroll
    for (int s = 2; s < 32; s <<= 1) {
#pragma unroll
        for (int i = 0; i < 8; i++)
            acc[i] += __shfl_xor_sync(0xffffffffu, acc[i], s);
    }

    if (node < N && lane < 2) {
        __align__(16) __half2 h[4];
#pragma unroll
        for (int j = 0; j < 4; j++) h[j] = __floats2half2_rn(acc[2 * j], acc[2 * j + 1]);
        *reinterpret_cast<int4*>(out + (size_t)node * 16 + fl * 8) =
            *reinterpret_cast<const int4*>(h);
    }
}

// ---- generic vectorized SPMM (fp32 path, layers 1/2/4) ---------------------
template<int F, int VEC, int GROUP, bool NORM>
__global__ void k_spmm(const float* __restrict__ z, const float* __restrict__ stats,
                       float* __restrict__ out, int N, int zs, int os) {
    constexpr int LPE = F / VEC;
    constexpr int EPI = GROUP / LPE;
    constexpr int NPW = 32 / GROUP;

    int lane = threadIdx.x & 31;
    int wid  = (blockIdx.x * blockDim.x + threadIdx.x) >> 5;
    int sub  = lane / GROUP;
    int gl   = lane % GROUP;
    int eg   = gl / LPE;
    int fl   = gl % LPE;

    int node = wid * NPW + sub;

    float m[VEC], rv[VEC];
#pragma unroll
    for (int i = 0; i < VEC; i++) { m[i] = 0.f; rv[i] = 1.f; }
    if (NORM) {
#pragma unroll
        for (int i = 0; i < VEC; i++) {
            m[i]  = stats[fl * VEC + i];
            rv[i] = stats[F + fl * VEC + i];
        }
    }

    int e0 = 0, e1 = 0;
    if (node < N) { e0 = g_off[node]; e1 = g_off[node + 1]; }

    float acc[VEC];
#pragma unroll
    for (int i = 0; i < VEC; i++) acc[i] = 0.f;

    for (int e = e0 + eg; e < e1; e += EPI) {
        int2 ed = g_edge[e];
        float w = __int_as_float(ed.y);
        const float* zp = z + (size_t)ed.x * zs + fl * VEC;
        float v[VEC];
        if (VEC == 4) {
            float4 t = *reinterpret_cast<const float4*>(zp);
            v[0] = t.x; v[1] = t.y; v[2] = t.z; v[3] = t.w;
        } else if (VEC == 2) {
            float2 t = *reinterpret_cast<const float2*>(zp);
            v[0] = t.x; v[1] = t.y;
        } else {
            v[0] = *zp;
        }
#pragma unroll
        for (int i = 0; i < VEC; i++) {
            float vi = NORM ? (v[i] - m[i]) * rv[i] : v[i];
            acc[i] = fmaf(w, vi, acc[i]);
        }
    }

#pragma unroll
    for (int s = LPE; s < GROUP; s <<= 1) {
#pragma unroll
        for (int i = 0; i < VEC; i++)
            acc[i] += __shfl_xor_sync(0xffffffffu, acc[i], s);
    }

    if (node < N && eg == 0) {
        float* op = out + (size_t)node * os + fl * VEC;
        if (VEC == 4) {
            *reinterpret_cast<float4*>(op) = make_float4(acc[0], acc[1], acc[2], acc[3]);
        } else if (VEC == 2) {
            *reinterpret_cast<float2*>(op) = make_float2(acc[0], acc[1]);
        } else {
            *op = acc[0];
        }
    }
}

// ---- Cheb combine (fp32 path, layers 1/2) ----------------------------------
template<int FI, int FO, int M>
__global__ void k_combine(const float* __restrict__ x, const float* __restrict__ stats,
                          const float* __restrict__ tx1, const float* __restrict__ s2,
                          const float* __restrict__ W, const float* __restrict__ b,
                          float* __restrict__ out, int N) {
    __shared__ float sW[3 * FI * FO];
    __shared__ float sb[FO];
    __shared__ float sm[FI], srv[FI];
    for (int i = threadIdx.x; i < FI * FO; i += blockDim.x) {
        float w0 = W[i], w1 = W[FI * FO + i], w2 = W[2 * FI * FO + i];
        sW[i] = w0 - w2;
        sW[FI * FO + i] = w1;
        sW[2 * FI * FO + i] = 2.f * w2;
    }
    if ((int)threadIdx.x < FO) sb[threadIdx.x] = b[threadIdx.x];
    if ((int)threadIdx.x < FI) {
        sm[threadIdx.x] = stats[threadIdx.x];
        srv[threadIdx.x] = stats[FI + threadIdx.x];
    }
    __syncthreads();
    int base = blockIdx.x * blockDim.x * M + threadIdx.x;
    int nn[M];
    float acc[M][FO];
#pragma unroll
    for (int i = 0; i < M; i++) {
        nn[i] = base + i * blockDim.x;
#pragma unroll
        for (int j = 0; j < FO; j++) acc[i][j] = sb[j];
    }
#pragma unroll 1
    for (int k = 0; k < FI; k++) {
        float xv[M], tv[M], sv[M];
#pragma unroll
        for (int i = 0; i < M; i++) {
            xv[i] = 0.f; tv[i] = 0.f; sv[i] = 0.f;
            if (nn[i] < N) {
                xv[i] = (x[nn[i] * FI + k] - sm[k]) * srv[k];
                tv[i] = tx1[nn[i] * FI + k];
                sv[i] = s2[nn[i] * FI + k];
            }
        }
#pragma unroll
        for (int j = 0; j < FO; j++) {
            float w0 = sW[k * FO + j];
            float w1 = sW[FI * FO + k * FO + j];
            float w2 = sW[2 * FI * FO + k * FO + j];
#pragma unroll
            for (int i = 0; i < M; i++)
                acc[i][j] = fmaf(xv[i], w0, fmaf(tv[i], w1, fmaf(sv[i], w2, acc[i][j])));
        }
    }
#pragma unroll
    for (int i = 0; i < M; i++)
        if (nn[i] < N) {
#pragma unroll
            for (int j = 0; j < FO; j++) out[nn[i] * FO + j] = fmaxf(acc[i][j], 0.f);
        }
}

// ---- layer-3 combine, half inputs (xn already normalized) ------------------
__global__ void __launch_bounds__(256) k_combine3(
    const __half* __restrict__ xn, const __half* __restrict__ t1,
    const __half* __restrict__ s2,
    const float* __restrict__ W, const float* __restrict__ b,
    float* __restrict__ out, int N) {
    constexpr int FI = 16, FO = 64;
    __shared__ float sW[3 * FI * FO];
    __shared__ float sb[FO];
    for (int i = threadIdx.x; i < FI * FO; i += blockDim.x) {
        float w0 = W[i], w1 = W[FI * FO + i], w2 = W[2 * FI * FO + i];
        sW[i] = w0 - w2;
        sW[FI * FO + i] = w1;
        sW[2 * FI * FO + i] = 2.f * w2;
    }
    if ((int)threadIdx.x < FO) sb[threadIdx.x] = b[threadIdx.x];
    __syncthreads();
    int node = blockIdx.x * blockDim.x + threadIdx.x;
    if (node >= N) return;

    float acc[FO];
#pragma unroll
    for (int j = 0; j < FO; j++) acc[j] = sb[j];

    const __half2* xp = reinterpret_cast<const __half2*>(xn + (size_t)node * FI);
    const __half2* tp = reinterpret_cast<const __half2*>(t1 + (size_t)node * FI);
    const __half2* sp = reinterpret_cast<const __half2*>(s2 + (size_t)node * FI);

#pragma unroll 1
    for (int kk = 0; kk < 8; kk++) {
        float2 xf = __half22float2(xp[kk]);
        float2 tf = __half22float2(tp[kk]);
        float2 sf = __half22float2(sp[kk]);
#pragma unroll
        for (int h = 0; h < 2; h++) {
            int k = kk * 2 + h;
            float xv = h ? xf.y : xf.x;
            float tv = h ? tf.y : tf.x;
            float sv = h ? sf.y : sf.x;
#pragma unroll
            for (int j = 0; j < FO; j++) {
                float w0 = sW[k * FO + j];
                float w1 = sW[FI * FO + k * FO + j];
                float w2 = sW[2 * FI * FO + k * FO + j];
                acc[j] = fmaf(xv, w0, fmaf(tv, w1, fmaf(sv, w2, acc[j])));
            }
        }
    }
    float4* op = reinterpret_cast<float4*>(out + (size_t)node * FO);
#pragma unroll
    for (int j = 0; j < FO / 4; j++)
        op[j] = make_float4(fmaxf(acc[4 * j], 0.f), fmaxf(acc[4 * j + 1], 0.f),
                            fmaxf(acc[4 * j + 2], 0.f), fmaxf(acc[4 * j + 3], 0.f));
}

// ---- layer4 projections: u = xin@(W0-W2), (q,r) = (xin@W1, xin@W2) ---------
__global__ void k_uqr(const float* __restrict__ x3, const float* __restrict__ stats,
                      const float* __restrict__ W, int N) {
    __shared__ float wu[64], wq[64], wr[64], sm[64], srv[64];
    int t = threadIdx.x;
    if (t < 64) {
        float w0 = W[t], w1 = W[64 + t], w2 = W[128 + t];
        wu[t] = w0 - w2; wq[t] = w1; wr[t] = w2;
        sm[t] = stats[t]; srv[t] = stats[64 + t];
    }
    __syncthreads();
    int n = blockIdx.x * blockDim.x + t;
    if (n >= N) return;
    float u = 0.f, q = 0.f, r = 0.f;
#pragma unroll
    for (int k = 0; k < 64; k++) {
        float xin = (x3[n * 64 + k] - sm[k]) * srv[k];
        u = fmaf(xin, wu[k], u);
        q = fmaf(xin, wq[k], q);
        r = fmaf(xin, wr[k], r);
    }
    g_u[n] = u;
    *reinterpret_cast<float2*>(&g_qr[n * 2]) = make_float2(q, r);
}

// ---- node MLP: xs(85) -> 40 -> 16 -> 1; x4 computed inline -----------------
__global__ void __launch_bounds__(128) k_nodemlp(
    const float* __restrict__ l1W, const float* __restrict__ l1b,
    const float* __restrict__ l2W, const float* __restrict__ l2b,
    const float* __restrict__ l3W, const float* __restrict__ l3b,
    const float* __restrict__ c4b,
    float* __restrict__ xo, int N) {
    __shared__ float sW1[85 * 40], sb1[40], sW2[40 * 16], sb2[16], sW3[16], sb3[1], sb4[1];
    for (int i = threadIdx.x; i < 85 * 40; i += blockDim.x) sW1[i] = l1W[i];
    for (int i = threadIdx.x; i < 40 * 16; i += blockDim.x) sW2[i] = l2W[i];
    if (threadIdx.x < 40) sb1[threadIdx.x] = l1b[threadIdx.x];
    if (threadIdx.x < 16) { sb2[threadIdx.x] = l2b[threadIdx.x]; sW3[threadIdx.x] = l3W[threadIdx.x]; }
    if (threadIdx.x == 0) { sb3[0] = l3b[0]; sb4[0] = c4b[0]; }
    __syncthreads();

    int base = blockIdx.x * blockDim.x * 2 + threadIdx.x;
    int n0 = base, n1 = base + blockDim.x;
    bool v0ok = n0 < N, v1ok = n1 < N;

    float h1[2][40];
#pragma unroll
    for (int j = 0; j < 40; j++) { h1[0][j] = sb1[j]; h1[1][j] = sb1[j]; }

#pragma unroll 1
    for (int k = 0; k < 4; k++) {
        float a = v0ok ? g_x1[n0 * 4 + k] : 0.f;
        float bb = v1ok ? g_x1[n1 * 4 + k] : 0.f;
#pragma unroll
        for (int j = 0; j < 40; j++) {
            float w = sW1[k * 40 + j];
            h1[0][j] = fmaf(a, w, h1[0][j]);
            h1[1][j] = fmaf(bb, w, h1[1][j]);
        }
    }
#pragma unroll 1
    for (int k = 0; k < 16; k++) {
        float a = v0ok ? g_x2[n0 * 16 + k] : 0.f;
        float bb = v1ok ? g_x2[n1 * 16 + k] : 0.f;
#pragma unroll
        for (int j = 0; j < 40; j++) {
            float w = sW1[(4 + k) * 40 + j];
            h1[0][j] = fmaf(a, w, h1[0][j]);
            h1[1][j] = fmaf(bb, w, h1[1][j]);
        }
    }
#pragma unroll 1
    for (int k = 0; k < 64; k++) {
        float a = v0ok ? g_x3[n0 * 64 + k] : 0.f;
        float bb = v1ok ? g_x3[n1 * 64 + k] : 0.f;
#pragma unroll
        for (int j = 0; j < 40; j++) {
            float w = sW1[(20 + k) * 40 + j];
            h1[0][j] = fmaf(a, w, h1[0][j]);
            h1[1][j] = fmaf(bb, w, h1[1][j]);
        }
    }
    {   // x4 = relu(u + Tq + 2*t + cheb4_b)
        float a = v0ok ? fmaxf(g_u[n0] + g_tqs[n0 * 2] + 2.f * g_t[n0] + sb4[0], 0.f) : 0.f;
        float bb = v1ok ? fmaxf(g_u[n1] + g_tqs[n1 * 2] + 2.f * g_t[n1] + sb4[0], 0.f) : 0.f;
#pragma unroll
        for (int j = 0; j < 40; j++) {
            float w = sW1[84 * 40 + j];
            h1[0][j] = fmaf(a, w, h1[0][j]);
            h1[1][j] = fmaf(bb, w, h1[1][j]);
        }
    }
#pragma unroll
    for (int j = 0; j < 40; j++) { h1[0][j] = fmaxf(h1[0][j], 0.f); h1[1][j] = fmaxf(h1[1][j], 0.f); }

    float h2[2][16];
#pragma unroll
    for (int j = 0; j < 16; j++) { h2[0][j] = sb2[j]; h2[1][j] = sb2[j]; }
#pragma unroll
    for (int k = 0; k < 40; k++) {
        float a = h1[0][k], bb = h1[1][k];
#pragma unroll
        for (int j = 0; j < 16; j++) {
            float w = sW2[k * 16 + j];
            h2[0][j] = fmaf(a, w, h2[0][j]);
            h2[1][j] = fmaf(bb, w, h2[1][j]);
        }
    }
    float o0 = sb3[0], o1 = sb3[0];
#pragma unroll
    for (int k = 0; k < 16; k++) {
        float w = sW3[k];
        o0 = fmaf(fmaxf(h2[0][k], 0.f), w, o0);
        o1 = fmaf(fmaxf(h2[1][k], 0.f), w, o1);
    }
    if (v0ok) xo[n0] = fmaxf(o0, 0.f);
    if (v1ok) xo[n1] = fmaxf(o1, 0.f);
}

// ---- edge MLPs -------------------------------------------------------------
__device__ __forceinline__ float edge_mlp(float s, float d, float a,
                                          const float* __restrict__ w1,
                                          const float* __restrict__ b1,
                                          const float* __restrict__ g,
                                          const float* __restrict__ be,
                                          const float* __restrict__ w2,
                                          const float* __restrict__ b2) {
    float h0 = fmaf(s, __ldg(&w1[0]), fmaf(d, __ldg(&w1[2]), fmaf(a, __ldg(&w1[4]), __ldg(&b1[0]))));
    float h1 = fmaf(s, __ldg(&w1[1]), fmaf(d, __ldg(&w1[3]), fmaf(a, __ldg(&w1[5]), __ldg(&b1[1]))));
    h0 = fmaxf(h0, 0.f);
    h1 = fmaxf(h1, 0.f);
    float m = 0.5f * (h0 + h1);
    float d0 = h0 - m, d1 = h1 - m;
    float var = 0.5f * (d0 * d0 + d1 * d1);
    float rs = rsqrtf(var + 1e-5f);
    h0 = fmaf(d0 * rs, __ldg(&g[0]), 0.f) + __ldg(&be[0]);
    h1 = fmaf(d1 * rs, __ldg(&g[1]), 0.f) + __ldg(&be[1]);
    return fmaf(h0, __ldg(&w2[0]), fmaf(h1, __ldg(&w2[1]), __ldg(&b2[0])));
}

__global__ void k_edge(const int* __restrict__ ei, const float* __restrict__ ea,
                       const float* __restrict__ xo,
                       const float* __restrict__ w11, const float* __restrict__ b11,
                       const float* __restrict__ g1, const float* __restrict__ be1,
                       const float* __restrict__ w12, const float* __restrict__ b12,
                       const float* __restrict__ w21, const float* __restrict__ b21,
                       const float* __restrict__ g2, const float* __restrict__ be2,
                       const float* __restrict__ w22, const float* __restrict__ b22,
                       float* __restrict__ out, int E) {
    int e = blockIdx.x * blockDim.x + threadIdx.x;
    if (e >= E) return;
    int r = ei[e];
    int c = ei[E + e];
    float s = __ldg(&xo[r]);
    float d = __ldg(&xo[c]);
    float a = ea[e];
    float o1 = fmaxf(edge_mlp(s, d, a, w11, b11, g1, be1, w12, b12), 0.f);
    float o2 = fmaxf(edge_mlp(s, d, o1, w21, b21, g2, be2, w22, b22), 0.f);
    out[e] = o2;
}

// ---------------------------------------------------------------------------
extern "C" void kernel_launch(void* const* d_in, const int* in_sizes, int n_in,
                              void* d_out, int out_size) {
    (void)n_in; (void)out_size;
    const float* x   = (const float*)d_in[0];
    const int*   ei  = (const int*)d_in[1];
    const float* ea  = (const float*)d_in[2];
    const float* c1W = (const float*)d_in[3];  const float* c1b = (const float*)d_in[4];
    const float* c2W = (const float*)d_in[5];  const float* c2b = (const float*)d_in[6];
    const float* c3W = (const float*)d_in[7];  const float* c3b = (const float*)d_in[8];
    const float* c4W = (const float*)d_in[9];  const float* c4b = (const float*)d_in[10];
    const float* l1W = (const float*)d_in[11]; const float* l1b = (const float*)d_in[12];
    const float* l2W = (const float*)d_in[13]; const float* l2b = (const float*)d_in[14];
    const float* l3W = (const float*)d_in[15]; const float* l3b = (const float*)d_in[16];
    const float* e1w1 = (const float*)d_in[17]; const float* e1b1 = (const float*)d_in[18];
    const float* e1g  = (const float*)d_in[19]; const float* e1be = (const float*)d_in[20];
    const float* e1w2 = (const float*)d_in[21]; const float* e1b2 = (const float*)d_in[22];
    const float* e2w1 = (const float*)d_in[23]; const float* e2b1 = (const float*)d_in[24];
    const float* e2g  = (const float*)d_in[25]; const float* e2be = (const float*)d_in[26];
    const float* e2w2 = (const float*)d_in[27]; const float* e2b2 = (const float*)d_in[28];

    int N = in_sizes[0];
    int E = in_sizes[1] / 2;
    float* out = (float*)d_out;
    float* xo = out;
    float* eaout = out + N;

    void* p;
    float *sums, *stats, *x1, *x2, *x3, *tx1, *s2, *qr, *tqs, *tt;
    __half *xn3, *th3, *sh3;
    cudaGetSymbolAddress(&p, g_sums);  sums  = (float*)p;
    cudaGetSymbolAddress(&p, g_stats); stats = (float*)p;
    cudaGetSymbolAddress(&p, g_x1);  x1  = (float*)p;
    cudaGetSymbolAddress(&p, g_x2);  x2  = (float*)p;
    cudaGetSymbolAddress(&p, g_x3);  x3  = (float*)p;
    cudaGetSymbolAddress(&p, g_tx1); tx1 = (float*)p;
    cudaGetSymbolAddress(&p, g_s2);  s2  = (float*)p;
    cudaGetSymbolAddress(&p, g_qr);  qr  = (float*)p;
    cudaGetSymbolAddress(&p, g_tqs); tqs = (float*)p;
    cudaGetSymbolAddress(&p, g_t);   tt  = (float*)p;
    cudaGetSymbolAddress(&p, g_xn3); xn3 = (__half*)p;
    cudaGetSymbolAddress(&p, g_th3); th3 = (__half*)p;
    cudaGetSymbolAddress(&p, g_sh3); sh3 = (__half*)p;

    int gN  = (N + 255) / 256;
    int gE  = (E + 255) / 256;
    int gC2 = (N + 255) / 256;
    int NB  = (N + 511) / 512;
    const int RG = 512;

    auto spmm_grid = [](int n, int group) {
        int npw = 32 / group;
        long long warps = (n + npw - 1) / npw;
        return (int)((warps * 32 + 255) / 256);
    };

    float* su1 = sums + 0;  float* st1 = stats + 0;
    float* su2 = sums + 2;  float* st2 = stats + 2;
    float* su3 = sums + 10; float* st3 = stats + 10;
    float* su4 = sums + 42; float* st4 = stats + 42;

    // ---- preprocessing ----
    k_zero<<<gN, 256>>>(N);
    k_count<<<gE, 256>>>(ei, ea, E);
    k_scanA<<<NB, 512>>>(N);
    k_scanB<<<1, 1024>>>(NB);
    k_scanC<<<gN, 256>>>(N, E);
    k_scatter<<<gE, 256>>>(ei, ea, E);

    // ---- layer 1: 1 -> 4 (fp32) ----
    k_reduce<1><<<RG, 256>>>(x, su1, N);
    k_finalize<<<1, 32>>>(su1, st1, 1, N);
    k_spmm<1, 1, 4, true ><<<spmm_grid(N, 4), 256>>>(x,   st1, tx1, N, 1, 1);
    k_spmm<1, 1, 4, false><<<spmm_grid(N, 4), 256>>>(tx1, nullptr, s2, N, 1, 1);
    k_combine<1, 4, 1><<<gN, 256>>>(x, st1, tx1, s2, c1W, c1b, x1, N);

    // ---- layer 2: 4 -> 16 (fp32) ----
    k_reduce<4><<<RG, 256>>>(x1, su2, N);
    k_finalize<<<1, 32>>>(su2, st2, 4, N);
    k_spmm<4, 4, 16, true ><<<spmm_grid(N, 16), 256>>>(x1,  st2, tx1, N, 4, 4);
    k_spmm<4, 4, 16, false><<<spmm_grid(N, 16), 256>>>(tx1, nullptr, s2, N, 4, 4);
    k_combine<4, 16, 2><<<gC2, 128>>>(x1, st2, tx1, s2, c2W, c2b, x2, N);

    // ---- layer 3: 16 -> 64 (fp16 SPMM path) ----
    k_reduce<16><<<RG, 256>>>(x2, su3, N);
    k_finalize<<<1, 32>>>(su3, st3, 16, N);
    k_prenorm16<<<(N * 8 + 255) / 256, 256>>>(x2, st3, xn3, N * 8);
    k_spmm16h<<<(int)(((long long)N * 32 + 255) / 256), 256>>>(xn3, th3, N);
    k_spmm16h<<<(int)(((long long)N * 32 + 255) / 256), 256>>>(th3, sh3, N);
    k_combine3<<<gN, 256>>>(xn3, th3, sh3, c3W, c3b, x3, N);

    // ---- layer 4: 64 -> 1 via spmm/matmul commute ----
    k_reduce<64><<<RG, 256>>>(x3, su4, N);
    k_finalize<<<1, 64>>>(su4, st4, 64, N);
    k_uqr<<<gN, 256>>>(x3, st4, c4W, N);
    k_spmm<2, 2, 8, false><<<spmm_grid(N, 8), 256>>>(qr, nullptr, tqs, N, 2, 2);      // (Tq, s)
    k_spmm<1, 1, 4, false><<<spmm_grid(N, 4), 256>>>(tqs + 1, nullptr, tt, N, 2, 1);  // t = spmm(s)

    // ---- node MLP and edge MLPs ----
    k_nodemlp<<<gC2, 128>>>(l1W, l1b, l2W, l2b, l3W, l3b, c4b, xo, N);
    k_edge<<<gE, 256>>>(ei, ea, xo,
                        e1w1, e1b1, e1g, e1be, e1w2, e1b2,
                        e2w1, e2b1, e2g, e2be, e2w2, e2b2,
                        eaout, E);
}